// round 1
// baseline (speedup 1.0000x reference)
#include <cuda_runtime.h>
#include <math.h>
#include <stdint.h>

#define BB 64
#define SS 1024
#define DD 256
#define NL 8
#define NC 1000
#define PI_F 3.14159265358979323846f
#define EPSF 1e-8f

// Scratch (device globals: no allocation allowed)
__device__ float g_x0[(size_t)BB * SS * DD];
__device__ float g_y0[(size_t)BB * SS * DD];
__device__ float g_xm_part[8][BB * DD];
__device__ float g_ym_part[8][BB * DD];
__device__ float g_dx[BB * DD];
__device__ float g_dy[BB * DD];
__device__ float g_pool_part[8][BB * DD];

__device__ __forceinline__ float gelu_f(float v) {
    return 0.5f * v * (1.0f + erff(v * 0.70710678118654752f));
}

// ---------------------------------------------------------------------------
// Kernel 1: fused GEMM (h = x @ W + b) + polar->cartesian epilogue.
// Tile: 128 m-rows x 64 d-channels (each d needs h columns d and d+256).
// 256 threads, thread tile 8m x 4d x 2 halves. Double-buffered smem, BK=8.
// Writes x0,y0 to scratch and per-tile column sums (deterministic partials).
// ---------------------------------------------------------------------------
__global__ void __launch_bounds__(256, 2) gemm_embed_kernel(
    const float* __restrict__ A, const float* __restrict__ W,
    const float* __restrict__ bias)
{
    const int mtile = blockIdx.x;   // 0..511
    const int dtile = blockIdx.y;   // 0..3
    const int m0 = mtile * 128;
    const int d0 = dtile * 64;
    const int tid = threadIdx.x;
    const int tx = tid & 15;        // d group (4 channels)
    const int ty = tid >> 4;        // m group (8 rows)

    __shared__ float As[2][8][128];
    __shared__ float Bs[2][2][8][64];
    __shared__ float sredx[16][64];
    __shared__ float sredy[16][64];

    float acc1[8][4], acc2[8][4];
#pragma unroll
    for (int i = 0; i < 8; i++)
#pragma unroll
        for (int j = 0; j < 4; j++) { acc1[i][j] = 0.f; acc2[i][j] = 0.f; }

    const int arow = tid >> 1;          // 0..127
    const int ak4  = (tid & 1) << 2;    // 0 or 4
    const float* Ap = A + (size_t)(m0 + arow) * 256 + ak4;

    const int bk = tid >> 5;            // 0..7
    const int bd = (tid & 31) << 1;     // 0..62
    const float* W1p = W + (size_t)bk * 512 + d0 + bd;
    const float* W2p = W1p + 256;

    // preload chunk 0
    float4 aV  = *(const float4*)Ap;
    float2 b1V = *(const float2*)W1p;
    float2 b2V = *(const float2*)W2p;
    As[0][ak4 + 0][arow] = aV.x; As[0][ak4 + 1][arow] = aV.y;
    As[0][ak4 + 2][arow] = aV.z; As[0][ak4 + 3][arow] = aV.w;
    Bs[0][0][bk][bd] = b1V.x; Bs[0][0][bk][bd + 1] = b1V.y;
    Bs[0][1][bk][bd] = b2V.x; Bs[0][1][bk][bd + 1] = b2V.y;
    __syncthreads();

    int cur = 0;
    for (int c = 0; c < 32; c++) {
        float4 aN; float2 b1N, b2N;
        if (c < 31) {
            aN  = *(const float4*)(Ap + (c + 1) * 8);
            b1N = *(const float2*)(W1p + (size_t)(c + 1) * 8 * 512);
            b2N = *(const float2*)(W2p + (size_t)(c + 1) * 8 * 512);
        }
#pragma unroll
        for (int kk = 0; kk < 8; kk++) {
            float4 ra0 = *(const float4*)&As[cur][kk][ty * 8];
            float4 ra1 = *(const float4*)&As[cur][kk][ty * 8 + 4];
            float4 rb1 = *(const float4*)&Bs[cur][0][kk][tx * 4];
            float4 rb2 = *(const float4*)&Bs[cur][1][kk][tx * 4];
            float ra[8]  = {ra0.x, ra0.y, ra0.z, ra0.w, ra1.x, ra1.y, ra1.z, ra1.w};
            float rbA[4] = {rb1.x, rb1.y, rb1.z, rb1.w};
            float rbB[4] = {rb2.x, rb2.y, rb2.z, rb2.w};
#pragma unroll
            for (int i = 0; i < 8; i++) {
#pragma unroll
                for (int j = 0; j < 4; j++) {
                    acc1[i][j] = fmaf(ra[i], rbA[j], acc1[i][j]);
                    acc2[i][j] = fmaf(ra[i], rbB[j], acc2[i][j]);
                }
            }
        }
        if (c < 31) {
            int nxt = cur ^ 1;
            As[nxt][ak4 + 0][arow] = aN.x; As[nxt][ak4 + 1][arow] = aN.y;
            As[nxt][ak4 + 2][arow] = aN.z; As[nxt][ak4 + 3][arow] = aN.w;
            Bs[nxt][0][bk][bd] = b1N.x; Bs[nxt][0][bk][bd + 1] = b1N.y;
            Bs[nxt][1][bk][bd] = b2N.x; Bs[nxt][1][bk][bd + 1] = b2N.y;
            __syncthreads();
            cur = nxt;
        }
    }

    // Epilogue: h -> (r, theta) -> (x0, y0), store + column sums over the
    // 128 m-rows of this tile (all rows share the same b since 128 | 1024).
    float b1v[4], b2v[4];
#pragma unroll
    for (int j = 0; j < 4; j++) {
        b1v[j] = bias[d0 + tx * 4 + j];
        b2v[j] = bias[256 + d0 + tx * 4 + j];
    }
    float csx[4] = {0, 0, 0, 0}, csy[4] = {0, 0, 0, 0};
#pragma unroll
    for (int i = 0; i < 8; i++) {
        int m = m0 + ty * 8 + i;
        float4 xo, yo;
#pragma unroll
        for (int j = 0; j < 4; j++) {
            float h1 = acc1[i][j] + b1v[j];
            float h2 = acc2[i][j] + b2v[j];
            float r = fabsf(h1) + 0.1f;
            float sn, cs;
            sincospif(h2, &sn, &cs);   // sin/cos of pi*h2, robust to fast-math
            float xv = r * cs, yv = r * sn;
            ((float*)&xo)[j] = xv;
            ((float*)&yo)[j] = yv;
            csx[j] += xv; csy[j] += yv;
        }
        *(float4*)&g_x0[(size_t)m * 256 + d0 + tx * 4] = xo;
        *(float4*)&g_y0[(size_t)m * 256 + d0 + tx * 4] = yo;
    }
#pragma unroll
    for (int j = 0; j < 4; j++) {
        sredx[ty][tx * 4 + j] = csx[j];
        sredy[ty][tx * 4 + j] = csy[j];
    }
    __syncthreads();
    if (tid < 64) {
        float sx = 0.f, sy = 0.f;
#pragma unroll
        for (int t = 0; t < 16; t++) { sx += sredx[t][tid]; sy += sredy[t][tid]; }
        int b = m0 >> 10;         // batch index
        int p = mtile & 7;        // partial slot within batch
        g_xm_part[p][b * 256 + d0 + tid] = sx;
        g_ym_part[p][b * 256 + d0 + tid] = sy;
    }
}

// ---------------------------------------------------------------------------
// Kernel 2: collapsed 8-layer recursion on the per-(b,d) means.
// One warp per (b,d); KAN hidden unit j handled by lane j; shfl reductions.
// ---------------------------------------------------------------------------
__global__ void __launch_bounds__(256) layers_kernel(
    const float* __restrict__ mag_w1, const float* __restrict__ mag_b1,
    const float* __restrict__ mag_w2, const float* __restrict__ mag_b2,
    const float* __restrict__ ph_w1,  const float* __restrict__ ph_b1,
    const float* __restrict__ ph_w2,  const float* __restrict__ ph_b2)
{
    int warp = (blockIdx.x * 256 + threadIdx.x) >> 5;   // 0..16383
    int lane = threadIdx.x & 31;
    if (warp >= BB * DD) return;

    float sx = 0.f, sy = 0.f;
#pragma unroll
    for (int p = 0; p < 8; p++) { sx += g_xm_part[p][warp]; sy += g_ym_part[p][warp]; }
    float xm = sx * (1.0f / 1024.0f);
    float ym = sy * (1.0f / 1024.0f);
    float DX = 0.f, DY = 0.f;

    for (int i = 0; i < NL; i++) {
        float r_agg = sqrtf(xm * xm + ym * ym + EPSF);
        float th = atan2f(ym, xm);
        float log_r = logf(r_agg + EPSF);
        // magnitude MLP (1 -> 32 -> 1), hidden unit = lane
        float hm = gelu_f(fmaf(log_r, mag_w1[i * 32 + lane], mag_b1[i * 32 + lane]));
        float lr = hm * mag_w2[i * 32 + lane];
        // phase MLP (2 -> 32 -> 2)
        float sn = sinf(th), cs = cosf(th);
        float hp = gelu_f(fmaf(sn, ph_w1[i * 64 + lane],
                          fmaf(cs, ph_w1[i * 64 + 32 + lane], ph_b1[i * 32 + lane])));
        float p0 = hp * ph_w2[i * 64 + lane * 2];
        float p1 = hp * ph_w2[i * 64 + lane * 2 + 1];
#pragma unroll
        for (int o = 16; o; o >>= 1) {
            lr += __shfl_xor_sync(0xffffffffu, lr, o);
            p0 += __shfl_xor_sync(0xffffffffu, p0, o);
            p1 += __shfl_xor_sync(0xffffffffu, p1, o);
        }
        lr += mag_b2[i];
        p0 += ph_b2[i * 2];
        p1 += ph_b2[i * 2 + 1];
        float r_trans = expf(lr);
        float norm = sqrtf(p0 * p0 + p1 * p1 + EPSF);
        float tht = atan2f(p0 / norm, p1 / norm);
        float dx = r_trans * cosf(tht);
        float dy = r_trans * sinf(tht);
        xm += dx; ym += dy; DX += dx; DY += dy;
    }
    if (lane == 0) { g_dx[warp] = DX; g_dy[warp] = DY; }
}

// ---------------------------------------------------------------------------
// Kernel 3: pooled r = mean_S sqrt((x0+DX)^2 + (y0+DY)^2 + EPS); 8 partials.
// ---------------------------------------------------------------------------
__global__ void __launch_bounds__(256) pool_kernel()
{
    int blk = blockIdx.x;       // 0..511, 128 m-rows each
    int m0 = blk * 128;
    int b = blk >> 3;
    int p = blk & 7;
    int d = threadIdx.x;
    float dxv = g_dx[b * 256 + d];
    float dyv = g_dy[b * 256 + d];
    const float* xp = &g_x0[(size_t)m0 * 256 + d];
    const float* yp = &g_y0[(size_t)m0 * 256 + d];
    float s = 0.f;
#pragma unroll 4
    for (int i = 0; i < 128; i++) {
        float xv = xp[(size_t)i * 256] + dxv;
        float yv = yp[(size_t)i * 256] + dyv;
        s += sqrtf(fmaf(xv, xv, fmaf(yv, yv, EPSF)));
    }
    g_pool_part[p][b * 256 + d] = s;
}

// ---------------------------------------------------------------------------
// Kernel 4: classifier. One CTA per batch row.
// ---------------------------------------------------------------------------
__global__ void __launch_bounds__(256) cls_kernel(
    const float* __restrict__ w1, const float* __restrict__ b1,
    const float* __restrict__ w2, const float* __restrict__ b2,
    float* __restrict__ out)
{
    int b = blockIdx.x;
    int tid = threadIdx.x;
    __shared__ float pooled[DD];
    __shared__ float hid[32];

    float sp = 0.f;
#pragma unroll
    for (int p = 0; p < 8; p++) sp += g_pool_part[p][b * 256 + tid];
    pooled[tid] = sp * (1.0f / 1024.0f);
    __syncthreads();

    if (tid < 32) {
        float a = b1[tid];
        for (int d = 0; d < DD; d++) a = fmaf(pooled[d], w1[d * 32 + tid], a);
        hid[tid] = gelu_f(a);
    }
    __syncthreads();

    for (int c = tid; c < NC; c += 256) {
        float a = b2[c];
#pragma unroll
        for (int k = 0; k < 32; k++) a = fmaf(hid[k], w2[k * NC + c], a);
        out[b * NC + c] = a;
    }
}

// ---------------------------------------------------------------------------
extern "C" void kernel_launch(void* const* d_in, const int* in_sizes, int n_in,
                              void* d_out, int out_size)
{
    const float* x       = (const float*)d_in[0];
    const float* embed_w = (const float*)d_in[1];
    const float* embed_b = (const float*)d_in[2];
    const float* mag_w1  = (const float*)d_in[3];
    const float* mag_b1  = (const float*)d_in[4];
    const float* mag_w2  = (const float*)d_in[5];
    const float* mag_b2  = (const float*)d_in[6];
    const float* ph_w1   = (const float*)d_in[7];
    const float* ph_b1   = (const float*)d_in[8];
    const float* ph_w2   = (const float*)d_in[9];
    const float* ph_b2   = (const float*)d_in[10];
    const float* cls_w1  = (const float*)d_in[11];
    const float* cls_b1  = (const float*)d_in[12];
    const float* cls_w2  = (const float*)d_in[13];
    const float* cls_b2  = (const float*)d_in[14];
    float* out = (float*)d_out;

    dim3 g1(512, 4);
    gemm_embed_kernel<<<g1, 256>>>(x, embed_w, embed_b);
    layers_kernel<<<2048, 256>>>(mag_w1, mag_b1, mag_w2, mag_b2,
                                 ph_w1, ph_b1, ph_w2, ph_b2);
    pool_kernel<<<512, 256>>>();
    cls_kernel<<<64, 256>>>(cls_w1, cls_b1, cls_w2, cls_b2, out);
}

// round 16
// speedup vs baseline: 1.4754x; 1.4754x over previous
#include <cuda_runtime.h>
#include <cuda_bf16.h>
#include <cuda_fp16.h>
#include <math.h>
#include <stdint.h>

#define BB 64
#define DPC 256
#define NL 8
#define NC 1000
#define EPSF 1e-8f
#define NTOT ((size_t)BB * 1024 * 256)

// ---------------- device scratch (no allocations allowed) -------------------
__device__ __align__(16) __nv_bfloat16 g_A_hi[NTOT];
__device__ __align__(16) __nv_bfloat16 g_A_lo[NTOT];
__device__ __align__(16) __nv_bfloat16 g_Wt_hi[512 * 256];
__device__ __align__(16) __nv_bfloat16 g_Wt_lo[512 * 256];
__device__ __half2 g_xy[NTOT];
__device__ float g_xm_part[8][BB * DPC];
__device__ float g_ym_part[8][BB * DPC];
__device__ float g_dx[BB * DPC];
__device__ float g_dy[BB * DPC];
__device__ float g_pool_part[8][BB * DPC];

__device__ __forceinline__ float gelu_f(float v) {
    return 0.5f * v * (1.0f + erff(v * 0.70710678118654752f));
}

// ---------------- mma.sync helpers (target-neutral, sm_80+) -----------------
__device__ __forceinline__ void ldsm4(uint32_t* r, uint32_t addr) {
    asm volatile("ldmatrix.sync.aligned.m8n8.x4.shared.b16 {%0,%1,%2,%3}, [%4];"
                 : "=r"(r[0]), "=r"(r[1]), "=r"(r[2]), "=r"(r[3]) : "r"(addr));
}
__device__ __forceinline__ void mma_bf16(float* c, const uint32_t* a, const uint32_t* b) {
    asm volatile("mma.sync.aligned.m16n8k16.row.col.f32.bf16.bf16.f32 "
                 "{%0,%1,%2,%3}, {%4,%5,%6,%7}, {%8,%9}, {%0,%1,%2,%3};"
                 : "+f"(c[0]), "+f"(c[1]), "+f"(c[2]), "+f"(c[3])
                 : "r"(a[0]), "r"(a[1]), "r"(a[2]), "r"(a[3]), "r"(b[0]), "r"(b[1]));
}
__device__ __forceinline__ void cp16(uint32_t dst, const void* src) {
    asm volatile("cp.async.cg.shared.global [%0], [%1], 16;" :: "r"(dst), "l"(src));
}

// SMEM layout (per pipeline stage, bytes)
#define AHI_OFF 0
#define ALO_OFF 16384
#define BHI_OFF 32768
#define BLO_OFF 65536
#define SSTRIDE 98304
#define DYN_SMEM 197632   // 2 stages + 1 KB alignment slack

// ---------------------------------------------------------------------------
// prep_a: fp32 x -> split bf16 (hi + residual lo), contiguous layout.
// ---------------------------------------------------------------------------
__global__ void __launch_bounds__(256) prep_a_kernel(const float* __restrict__ x)
{
    size_t i = (size_t)blockIdx.x * 256 + threadIdx.x;   // one float4 per thread
    float4 v = ((const float4*)x)[i];
    float vv[4] = {v.x, v.y, v.z, v.w};
    __nv_bfloat16 h[4], l[4];
#pragma unroll
    for (int j = 0; j < 4; j++) {
        h[j] = __float2bfloat16(vv[j]);
        l[j] = __float2bfloat16(vv[j] - __bfloat162float(h[j]));
    }
    __nv_bfloat162* hp = (__nv_bfloat162*)g_A_hi;
    __nv_bfloat162* lp = (__nv_bfloat162*)g_A_lo;
    hp[i * 2]     = __nv_bfloat162(h[0], h[1]);
    hp[i * 2 + 1] = __nv_bfloat162(h[2], h[3]);
    lp[i * 2]     = __nv_bfloat162(l[0], l[1]);
    lp[i * 2 + 1] = __nv_bfloat162(l[2], l[3]);
}

// ---------------------------------------------------------------------------
// prep_w: transpose + channel-pair permute + split bf16.
// Tile t: rows [t*256, t*256+128) = h1 cols of channels t*128+j,
//         rows [t*256+128, ...)   = h2 cols of same channels.
// ---------------------------------------------------------------------------
__global__ void __launch_bounds__(256) prep_w_kernel(const float* __restrict__ W)
{
    int p = blockIdx.x;          // 0..511 output row
    int k = threadIdx.x;         // 0..255
    int t = p >> 8, r = p & 255;
    int col = (r < 128) ? (t * 128 + r) : (256 + t * 128 + (r - 128));
    float v = W[(size_t)k * 512 + col];
    __nv_bfloat16 hi = __float2bfloat16(v);
    g_Wt_hi[p * 256 + k] = hi;
    g_Wt_lo[p * 256 + k] = __float2bfloat16(v - __bfloat162float(hi));
}

// ---------------------------------------------------------------------------
// GEMM (mma.sync bf16, split-precision) + fused polar epilogue.
// Grid (512 m-tiles, 2 channel-tiles), 512 threads (16 warps, 4x4 warp grid).
// ---------------------------------------------------------------------------
__global__ void __launch_bounds__(512, 1) gemm_tc_kernel(const float* __restrict__ bias)
{
    extern __shared__ __align__(16) uint8_t dsm[];
    uint32_t sb_raw;
    asm("{ .reg .u64 t; cvta.to.shared.u64 t, %1; cvt.u32.u64 %0, t; }"
        : "=r"(sb_raw) : "l"(dsm));
    const uint32_t sb = (sb_raw + 1023u) & ~1023u;

    const int tid = threadIdx.x;
    const int lane = tid & 31, wid = tid >> 5;
    const int wm = wid >> 2, wn = wid & 3;
    const int mtile = blockIdx.x, t = blockIdx.y;
    const int m0 = mtile * 128, ch0 = t * 128;

    float acc[2][8][4];
#pragma unroll
    for (int a = 0; a < 2; a++)
#pragma unroll
        for (int b = 0; b < 8; b++)
#pragma unroll
            for (int c = 0; c < 4; c++) acc[a][b][c] = 0.f;

    // prefetch assignments
    const int ra = tid >> 2, ua = (tid & 3) * 2, swa = ra & 7;
    const int rb = tid >> 1, ub = (tid & 1) * 4, swb = rb & 7;
    const __nv_bfloat16* gAh = g_A_hi + (size_t)(m0 + ra) * 256;
    const __nv_bfloat16* gAl = g_A_lo + (size_t)(m0 + ra) * 256;
    const __nv_bfloat16* gBh = g_Wt_hi + ((size_t)t * 256 + rb) * 256;
    const __nv_bfloat16* gBl = g_Wt_lo + ((size_t)t * 256 + rb) * 256;

    auto prefetch = [&](int c, int st) {
        uint32_t s0 = sb + st * SSTRIDE;
        const __nv_bfloat16* pa = gAh + c * 64;
        const __nv_bfloat16* pl = gAl + c * 64;
        cp16(s0 + AHI_OFF + ra * 128 + (((ua    ) ^ swa) << 4), pa + (ua    ) * 8);
        cp16(s0 + AHI_OFF + ra * 128 + (((ua + 1) ^ swa) << 4), pa + (ua + 1) * 8);
        cp16(s0 + ALO_OFF + ra * 128 + (((ua    ) ^ swa) << 4), pl + (ua    ) * 8);
        cp16(s0 + ALO_OFF + ra * 128 + (((ua + 1) ^ swa) << 4), pl + (ua + 1) * 8);
        const __nv_bfloat16* pb = gBh + c * 64;
        const __nv_bfloat16* pq = gBl + c * 64;
#pragma unroll
        for (int u = 0; u < 4; u++) {
            int uu = ub + u;
            cp16(s0 + BHI_OFF + rb * 128 + ((uu ^ swb) << 4), pb + uu * 8);
            cp16(s0 + BLO_OFF + rb * 128 + ((uu ^ swb) << 4), pq + uu * 8);
        }
    };

    const int jj = lane >> 3, rr = lane & 7;

    auto compute = [&](int st) {
        uint32_t s0 = sb + st * SSTRIDE;
#pragma unroll
        for (int kk = 0; kk < 4; kk++) {
            uint32_t ah[2][4], al[2][4], bf[16], boff[4];
#pragma unroll
            for (int mt = 0; mt < 2; mt++) {
                int row = wm * 32 + mt * 16 + (jj & 1) * 8 + rr;
                int unit = kk * 2 + (jj >> 1);
                uint32_t off = (uint32_t)row * 128 + ((uint32_t)(unit ^ (row & 7)) << 4);
                ldsm4(ah[mt], s0 + AHI_OFF + off);
                ldsm4(al[mt], s0 + ALO_OFF + off);
            }
#pragma unroll
            for (int i = 0; i < 4; i++) {
                int n = wn * 64 + i * 16 + (jj >> 1) * 8 + rr;
                int unit = kk * 2 + (jj & 1);
                boff[i] = (uint32_t)n * 128 + ((uint32_t)(unit ^ (n & 7)) << 4);
                ldsm4(&bf[i * 4], s0 + BHI_OFF + boff[i]);
            }
#pragma unroll
            for (int mt = 0; mt < 2; mt++)
#pragma unroll
                for (int nt = 0; nt < 8; nt++)
                    mma_bf16(acc[mt][nt], ah[mt], &bf[nt * 2]);
#pragma unroll
            for (int mt = 0; mt < 2; mt++)
#pragma unroll
                for (int nt = 0; nt < 8; nt++)
                    mma_bf16(acc[mt][nt], al[mt], &bf[nt * 2]);
#pragma unroll
            for (int i = 0; i < 4; i++)
                ldsm4(&bf[i * 4], s0 + BLO_OFF + boff[i]);
#pragma unroll
            for (int mt = 0; mt < 2; mt++)
#pragma unroll
                for (int nt = 0; nt < 8; nt++)
                    mma_bf16(acc[mt][nt], ah[mt], &bf[nt * 2]);
        }
    };

    prefetch(0, 0);
    asm volatile("cp.async.commit_group;");
#pragma unroll 1
    for (int c = 0; c < 4; c++) {
        if (c < 3) {
            prefetch(c + 1, (c + 1) & 1);
            asm volatile("cp.async.commit_group;");
            asm volatile("cp.async.wait_group 1;");
        } else {
            asm volatile("cp.async.wait_group 0;");
        }
        __syncthreads();
        compute(c & 1);
        __syncthreads();
    }

    // ---------------- epilogue: stage h to smem, polar, half2 out -----------
    const int g = lane >> 2, tg = lane & 3;
#pragma unroll
    for (int mt = 0; mt < 2; mt++) {
        int r0 = wm * 32 + mt * 16 + g;
#pragma unroll
        for (int nt = 0; nt < 8; nt++) {
            int cb = wn * 64 + nt * 8 + tg * 2;
            uint32_t a0 = sb + ((uint32_t)r0 * 258 + cb) * 4;
            uint32_t a1 = sb + ((uint32_t)(r0 + 8) * 258 + cb) * 4;
            asm volatile("st.shared.v2.f32 [%0], {%1,%2};"
                         :: "r"(a0), "f"(acc[mt][nt][0]), "f"(acc[mt][nt][1]));
            asm volatile("st.shared.v2.f32 [%0], {%1,%2};"
                         :: "r"(a1), "f"(acc[mt][nt][2]), "f"(acc[mt][nt][3]));
        }
    }
    __syncthreads();

    const int ch = tid >> 2, q = tid & 3;
    const int p = mtile & 7, bidx = mtile >> 3;
    float b1v = bias[ch0 + ch];
    float b2v = bias[256 + ch0 + ch];
    float csx = 0.f, csy = 0.f;
#pragma unroll 4
    for (int i = 0; i < 32; i++) {
        int row = i * 4 + q;
        float h1, h2;
        asm volatile("ld.shared.f32 %0, [%1];" : "=f"(h1)
                     : "r"(sb + ((uint32_t)row * 258 + ch) * 4));
        asm volatile("ld.shared.f32 %0, [%1];" : "=f"(h2)
                     : "r"(sb + ((uint32_t)row * 258 + 128 + ch) * 4));
        h1 += b1v; h2 += b2v;
        float r = fabsf(h1) + 0.1f;
        float sn, cs;
        sincospif(h2, &sn, &cs);
        float xv = r * cs, yv = r * sn;
        g_xy[(size_t)(m0 + row) * 256 + ch0 + ch] = __floats2half2_rn(xv, yv);
        csx += xv; csy += yv;
    }
    csx += __shfl_xor_sync(0xffffffffu, csx, 1);
    csx += __shfl_xor_sync(0xffffffffu, csx, 2);
    csy += __shfl_xor_sync(0xffffffffu, csy, 1);
    csy += __shfl_xor_sync(0xffffffffu, csy, 2);
    if ((lane & 3) == 0) {
        g_xm_part[p][bidx * 256 + ch0 + ch] = csx;
        g_ym_part[p][bidx * 256 + ch0 + ch] = csy;
    }
}

// ---------------------------------------------------------------------------
// Collapsed 8-layer recursion on per-(b,d) means. One warp per (b,d).
// ---------------------------------------------------------------------------
__global__ void __launch_bounds__(256) layers_kernel(
    const float* __restrict__ mag_w1, const float* __restrict__ mag_b1,
    const float* __restrict__ mag_w2, const float* __restrict__ mag_b2,
    const float* __restrict__ ph_w1,  const float* __restrict__ ph_b1,
    const float* __restrict__ ph_w2,  const float* __restrict__ ph_b2)
{
    int warp = (blockIdx.x * 256 + threadIdx.x) >> 5;
    int lane = threadIdx.x & 31;
    if (warp >= BB * DPC) return;

    float sx = 0.f, sy = 0.f;
#pragma unroll
    for (int p = 0; p < 8; p++) { sx += g_xm_part[p][warp]; sy += g_ym_part[p][warp]; }
    float xm = sx * (1.0f / 1024.0f);
    float ym = sy * (1.0f / 1024.0f);
    float DX = 0.f, DY = 0.f;

    for (int i = 0; i < NL; i++) {
        float r_agg = sqrtf(xm * xm + ym * ym + EPSF);
        float th = atan2f(ym, xm);
        float log_r = logf(r_agg + EPSF);
        float hm = gelu_f(fmaf(log_r, mag_w1[i * 32 + lane], mag_b1[i * 32 + lane]));
        float lr = hm * mag_w2[i * 32 + lane];
        float sn = sinf(th), cs = cosf(th);
        float hp = gelu_f(fmaf(sn, ph_w1[i * 64 + lane],
                          fmaf(cs, ph_w1[i * 64 + 32 + lane], ph_b1[i * 32 + lane])));
        float p0 = hp * ph_w2[i * 64 + lane * 2];
        float p1 = hp * ph_w2[i * 64 + lane * 2 + 1];
#pragma unroll
        for (int o = 16; o; o >>= 1) {
            lr += __shfl_xor_sync(0xffffffffu, lr, o);
            p0 += __shfl_xor_sync(0xffffffffu, p0, o);
            p1 += __shfl_xor_sync(0xffffffffu, p1, o);
        }
        lr += mag_b2[i];
        p0 += ph_b2[i * 2];
        p1 += ph_b2[i * 2 + 1];
        float r_trans = expf(lr);
        float norm = sqrtf(p0 * p0 + p1 * p1 + EPSF);
        float tht = atan2f(p0 / norm, p1 / norm);
        float dx = r_trans * cosf(tht);
        float dy = r_trans * sinf(tht);
        xm += dx; ym += dy; DX += dx; DY += dy;
    }
    if (lane == 0) { g_dx[warp] = DX; g_dy[warp] = DY; }
}

// ---------------------------------------------------------------------------
// Pool: mean_S sqrt((x0+DX)^2 + (y0+DY)^2 + EPS), coalesced half2 reads.
// ---------------------------------------------------------------------------
__global__ void __launch_bounds__(256) pool_kernel()
{
    int blk = blockIdx.x;
    int m0 = blk * 128;
    int b = blk >> 3, p = blk & 7;
    int c = threadIdx.x;
    float dxv = g_dx[b * 256 + c];
    float dyv = g_dy[b * 256 + c];
    const __half2* xp = &g_xy[(size_t)m0 * 256 + c];
    float s = 0.f;
#pragma unroll 8
    for (int i = 0; i < 128; i++) {
        float2 f = __half22float2(xp[(size_t)i * 256]);
        float xv = f.x + dxv, yv = f.y + dyv;
        s += sqrtf(fmaf(xv, xv, fmaf(yv, yv, EPSF)));
    }
    g_pool_part[p][b * 256 + c] = s;
}

// ---------------------------------------------------------------------------
// Classifier. One CTA per batch row.
// ---------------------------------------------------------------------------
__global__ void __launch_bounds__(256) cls_kernel(
    const float* __restrict__ w1, const float* __restrict__ b1,
    const float* __restrict__ w2, const float* __restrict__ b2,
    float* __restrict__ out)
{
    int b = blockIdx.x;
    int tid = threadIdx.x;
    __shared__ float pooled[DPC];
    __shared__ float hpart[8][32];
    __shared__ float hid[32];

    float sp = 0.f;
#pragma unroll
    for (int p = 0; p < 8; p++) sp += g_pool_part[p][b * 256 + tid];
    pooled[tid] = sp * (1.0f / 1024.0f);
    __syncthreads();

    {
        int j = tid & 31, chk = tid >> 5;
        float a = 0.f;
#pragma unroll
        for (int d = 0; d < 32; d++)
            a = fmaf(pooled[chk * 32 + d], w1[(chk * 32 + d) * 32 + j], a);
        hpart[chk][j] = a;
    }
    __syncthreads();
    if (tid < 32) {
        float s = b1[tid];
#pragma unroll
        for (int c = 0; c < 8; c++) s += hpart[c][tid];
        hid[tid] = gelu_f(s);
    }
    __syncthreads();

    for (int c = tid; c < NC; c += 256) {
        float a = b2[c];
#pragma unroll
        for (int k = 0; k < 32; k++) a = fmaf(hid[k], w2[k * NC + c], a);
        out[b * NC + c] = a;
    }
}

// ---------------------------------------------------------------------------
extern "C" void kernel_launch(void* const* d_in, const int* in_sizes, int n_in,
                              void* d_out, int out_size)
{
    const float* x       = (const float*)d_in[0];
    const float* embed_w = (const float*)d_in[1];
    const float* embed_b = (const float*)d_in[2];
    const float* mag_w1  = (const float*)d_in[3];
    const float* mag_b1  = (const float*)d_in[4];
    const float* mag_w2  = (const float*)d_in[5];
    const float* mag_b2  = (const float*)d_in[6];
    const float* ph_w1   = (const float*)d_in[7];
    const float* ph_b1   = (const float*)d_in[8];
    const float* ph_w2   = (const float*)d_in[9];
    const float* ph_b2   = (const float*)d_in[10];
    const float* cls_w1  = (const float*)d_in[11];
    const float* cls_b1  = (const float*)d_in[12];
    const float* cls_w2  = (const float*)d_in[13];
    const float* cls_b2  = (const float*)d_in[14];
    float* out = (float*)d_out;

    cudaFuncSetAttribute(gemm_tc_kernel,
                         cudaFuncAttributeMaxDynamicSharedMemorySize, DYN_SMEM);

    prep_a_kernel<<<16384, 256>>>(x);
    prep_w_kernel<<<512, 256>>>(embed_w);
    gemm_tc_kernel<<<dim3(512, 2), 512, DYN_SMEM>>>(embed_b);
    layers_kernel<<<2048, 256>>>(mag_w1, mag_b1, mag_w2, mag_b2,
                                 ph_w1, ph_b1, ph_w2, ph_b2);
    pool_kernel<<<512, 256>>>();
    cls_kernel<<<64, 256>>>(cls_w1, cls_b1, cls_w2, cls_b2, out);
}